// round 2
// baseline (speedup 1.0000x reference)
#include <cuda_runtime.h>
#include <cstdint>

#define NN    50000
#define NE    800000
#define HD    64
#define KIN   136    // 2*HD + EDIM
#define MH    128
#define TILE  64

// scratch: aggregated messages per node
__device__ float g_agg[(size_t)NN * HD];

// ---------------------------------------------------------------------------
// zero the aggregation buffer
// ---------------------------------------------------------------------------
__global__ void zero_agg_kernel() {
    int i = blockIdx.x * blockDim.x + threadIdx.x;
    const int n4 = NN * HD / 4;
    if (i < n4) {
        float4 z = make_float4(0.f, 0.f, 0.f, 0.f);
        reinterpret_cast<float4*>(g_agg)[i] = z;
    }
}

// ---------------------------------------------------------------------------
// Edge kernel: per 64-edge tile
//   X[64,136] = gather(h[src], h[dst], edge_attr)
//   Hd = relu(X @ eW1 + eb1)          [64,128]
//   M  = Hd @ eW2 + eb2               [64,64]
//   red.global.add M rows into g_agg[dst]
// Weights stay resident in SMEM across a grid-stride loop over tiles.
// NOTE: edge_index is int32 on device (JAX default config downcasts int64).
// ---------------------------------------------------------------------------
__global__ __launch_bounds__(256, 1)
void edge_kernel(const float* __restrict__ h,
                 const int* __restrict__ ei,
                 const float* __restrict__ ea,
                 const float* __restrict__ eW1, const float* __restrict__ eb1,
                 const float* __restrict__ eW2, const float* __restrict__ eb2)
{
    extern __shared__ float sm[];
    float* sW1 = sm;                      // 136*128
    float* sW2 = sW1 + KIN * MH;          // 128*64
    float* sX  = sW2 + MH * HD;           // 64*136
    float* sH  = sX  + TILE * KIN;        // 64*132 (padded)
    int*   sSrc = (int*)(sH + TILE * 132);
    int*   sDst = sSrc + TILE;

    const int tid = threadIdx.x;

    for (int i = tid; i < KIN * MH; i += 256) sW1[i] = eW1[i];
    for (int i = tid; i < MH * HD;  i += 256) sW2[i] = eW2[i];

    const int tx  = tid & 31, ty  = tid >> 5;   // phase1: 8 edges x 4 cols
    const int tx2 = tid & 15, ty2 = tid >> 4;   // phase2: 4 edges x 4 cols

    float b1r[4], b2r[4];
    #pragma unroll
    for (int j = 0; j < 4; j++) {
        b1r[j] = eb1[tx * 4 + j];
        b2r[j] = eb2[tx2 * 4 + j];
    }

    const int numTiles = NE / TILE;
    for (int tile = blockIdx.x; tile < numTiles; tile += gridDim.x) {
        const int e0 = tile * TILE;
        __syncthreads();   // previous iter's phase2 reads of sH/sDst done

        if (tid < TILE) {
            int s = ei[e0 + tid];
            int d = ei[NE + e0 + tid];
            // clamp defensively: a bad index becomes wrong-answer, not a crash
            sSrc[tid] = min(max(s, 0), NN - 1);
            sDst[tid] = min(max(d, 0), NN - 1);
        }
        __syncthreads();

        // gather X tile
        for (int i = tid; i < TILE * KIN; i += 256) {
            int r = i / KIN;
            int k = i - r * KIN;
            float v;
            if (k < HD)            v = h[(size_t)sSrc[r] * HD + k];
            else if (k < 2 * HD)   v = h[(size_t)sDst[r] * HD + (k - HD)];
            else                   v = ea[(size_t)(e0 + r) * 8 + (k - 2 * HD)];
            sX[i] = v;
        }
        __syncthreads();

        // phase 1: [64,136] @ [136,128]
        float acc[8][4];
        #pragma unroll
        for (int i = 0; i < 8; i++)
            #pragma unroll
            for (int j = 0; j < 4; j++) acc[i][j] = 0.f;

        for (int k = 0; k < KIN; k += 4) {
            const float4 bv0 = *(const float4*)&sW1[(k + 0) * MH + tx * 4];
            const float4 bv1 = *(const float4*)&sW1[(k + 1) * MH + tx * 4];
            const float4 bv2 = *(const float4*)&sW1[(k + 2) * MH + tx * 4];
            const float4 bv3 = *(const float4*)&sW1[(k + 3) * MH + tx * 4];
            #pragma unroll
            for (int i = 0; i < 8; i++) {
                const float4 av = *(const float4*)&sX[(ty * 8 + i) * KIN + k];
                acc[i][0] = fmaf(av.w, bv3.x, fmaf(av.z, bv2.x, fmaf(av.y, bv1.x, fmaf(av.x, bv0.x, acc[i][0]))));
                acc[i][1] = fmaf(av.w, bv3.y, fmaf(av.z, bv2.y, fmaf(av.y, bv1.y, fmaf(av.x, bv0.y, acc[i][1]))));
                acc[i][2] = fmaf(av.w, bv3.z, fmaf(av.z, bv2.z, fmaf(av.y, bv1.z, fmaf(av.x, bv0.z, acc[i][2]))));
                acc[i][3] = fmaf(av.w, bv3.w, fmaf(av.z, bv2.w, fmaf(av.y, bv1.w, fmaf(av.x, bv0.w, acc[i][3]))));
            }
        }

        // relu + bias -> sH
        #pragma unroll
        for (int i = 0; i < 8; i++) {
            float4 v;
            v.x = fmaxf(acc[i][0] + b1r[0], 0.f);
            v.y = fmaxf(acc[i][1] + b1r[1], 0.f);
            v.z = fmaxf(acc[i][2] + b1r[2], 0.f);
            v.w = fmaxf(acc[i][3] + b1r[3], 0.f);
            *(float4*)&sH[(ty * 8 + i) * 132 + tx * 4] = v;
        }
        __syncthreads();

        // phase 2: [64,128] @ [128,64]
        float a2[4][4];
        #pragma unroll
        for (int i = 0; i < 4; i++)
            #pragma unroll
            for (int j = 0; j < 4; j++) a2[i][j] = 0.f;

        for (int k = 0; k < MH; k += 4) {
            const float4 bv0 = *(const float4*)&sW2[(k + 0) * HD + tx2 * 4];
            const float4 bv1 = *(const float4*)&sW2[(k + 1) * HD + tx2 * 4];
            const float4 bv2 = *(const float4*)&sW2[(k + 2) * HD + tx2 * 4];
            const float4 bv3 = *(const float4*)&sW2[(k + 3) * HD + tx2 * 4];
            #pragma unroll
            for (int i = 0; i < 4; i++) {
                const float4 av = *(const float4*)&sH[(ty2 * 4 + i) * 132 + k];
                a2[i][0] = fmaf(av.w, bv3.x, fmaf(av.z, bv2.x, fmaf(av.y, bv1.x, fmaf(av.x, bv0.x, a2[i][0]))));
                a2[i][1] = fmaf(av.w, bv3.y, fmaf(av.z, bv2.y, fmaf(av.y, bv1.y, fmaf(av.x, bv0.y, a2[i][1]))));
                a2[i][2] = fmaf(av.w, bv3.z, fmaf(av.z, bv2.z, fmaf(av.y, bv1.z, fmaf(av.x, bv0.z, a2[i][2]))));
                a2[i][3] = fmaf(av.w, bv3.w, fmaf(av.z, bv2.w, fmaf(av.y, bv1.w, fmaf(av.x, bv0.w, a2[i][3]))));
            }
        }

        // scatter-add into g_agg via vectorized reduction
        #pragma unroll
        for (int i = 0; i < 4; i++) {
            const int r = ty2 * 4 + i;
            float* p = g_agg + (size_t)sDst[r] * HD + tx2 * 4;
            float v0 = a2[i][0] + b2r[0];
            float v1 = a2[i][1] + b2r[1];
            float v2 = a2[i][2] + b2r[2];
            float v3 = a2[i][3] + b2r[3];
            asm volatile("red.global.add.v4.f32 [%0], {%1, %2, %3, %4};"
                         :: "l"(p), "f"(v0), "f"(v1), "f"(v2), "f"(v3)
                         : "memory");
        }
    }
}

// ---------------------------------------------------------------------------
// Node kernel: per 64-node tile
//   U[64,128] = [h | agg]
//   Hd = relu(U @ nW1 + nb1)
//   upd = Hd @ nW2 + nb2
//   out = LayerNorm(h + upd) * g + b
// ---------------------------------------------------------------------------
__global__ __launch_bounds__(256, 1)
void node_kernel(const float* __restrict__ h,
                 const float* __restrict__ nW1, const float* __restrict__ nb1,
                 const float* __restrict__ nW2, const float* __restrict__ nb2,
                 const float* __restrict__ lg,  const float* __restrict__ lb,
                 float* __restrict__ out)
{
    extern __shared__ float sm[];
    float* sW1 = sm;                     // 128*128
    float* sW2 = sW1 + MH * MH;          // 128*64
    float* sU  = sW2 + MH * HD;          // 64*128
    float* sH  = sU  + TILE * MH;        // 64*132
    float* sO  = sH  + TILE * 132;       // 64*65 (padded: avoids 32-way conflict)
    float* sMu = sO  + TILE * 65;        // 64
    float* sRs = sMu + TILE;             // 64
    float* sG  = sRs + TILE;             // 64
    float* sB  = sG  + TILE;             // 64

    const int tid = threadIdx.x;

    for (int i = tid; i < MH * MH; i += 256) sW1[i] = nW1[i];
    for (int i = tid; i < MH * HD; i += 256) sW2[i] = nW2[i];
    if (tid < HD) { sG[tid] = lg[tid]; sB[tid] = lb[tid]; }

    const int tx  = tid & 31, ty  = tid >> 5;
    const int tx2 = tid & 15, ty2 = tid >> 4;

    float b1r[4], b2r[4];
    #pragma unroll
    for (int j = 0; j < 4; j++) {
        b1r[j] = nb1[tx * 4 + j];
        b2r[j] = nb2[tx2 * 4 + j];
    }

    const int numTiles = (NN + TILE - 1) / TILE;
    for (int tile = blockIdx.x; tile < numTiles; tile += gridDim.x) {
        const int n0 = tile * TILE;
        __syncthreads();

        // gather U = [h | agg]
        for (int i = tid; i < TILE * MH; i += 256) {
            int r = i >> 7;
            int k = i & 127;
            int node = n0 + r;
            if (node >= NN) node = NN - 1;     // clamp; stores guarded below
            sU[i] = (k < HD) ? h[(size_t)node * HD + k]
                             : g_agg[(size_t)node * HD + (k - HD)];
        }
        __syncthreads();

        // phase 1: [64,128] @ [128,128]
        float acc[8][4];
        #pragma unroll
        for (int i = 0; i < 8; i++)
            #pragma unroll
            for (int j = 0; j < 4; j++) acc[i][j] = 0.f;

        for (int k = 0; k < MH; k += 4) {
            const float4 bv0 = *(const float4*)&sW1[(k + 0) * MH + tx * 4];
            const float4 bv1 = *(const float4*)&sW1[(k + 1) * MH + tx * 4];
            const float4 bv2 = *(const float4*)&sW1[(k + 2) * MH + tx * 4];
            const float4 bv3 = *(const float4*)&sW1[(k + 3) * MH + tx * 4];
            #pragma unroll
            for (int i = 0; i < 8; i++) {
                const float4 av = *(const float4*)&sU[(ty * 8 + i) * MH + k];
                acc[i][0] = fmaf(av.w, bv3.x, fmaf(av.z, bv2.x, fmaf(av.y, bv1.x, fmaf(av.x, bv0.x, acc[i][0]))));
                acc[i][1] = fmaf(av.w, bv3.y, fmaf(av.z, bv2.y, fmaf(av.y, bv1.y, fmaf(av.x, bv0.y, acc[i][1]))));
                acc[i][2] = fmaf(av.w, bv3.z, fmaf(av.z, bv2.z, fmaf(av.y, bv1.z, fmaf(av.x, bv0.z, acc[i][2]))));
                acc[i][3] = fmaf(av.w, bv3.w, fmaf(av.z, bv2.w, fmaf(av.y, bv1.w, fmaf(av.x, bv0.w, acc[i][3]))));
            }
        }

        #pragma unroll
        for (int i = 0; i < 8; i++) {
            float4 v;
            v.x = fmaxf(acc[i][0] + b1r[0], 0.f);
            v.y = fmaxf(acc[i][1] + b1r[1], 0.f);
            v.z = fmaxf(acc[i][2] + b1r[2], 0.f);
            v.w = fmaxf(acc[i][3] + b1r[3], 0.f);
            *(float4*)&sH[(ty * 8 + i) * 132 + tx * 4] = v;
        }
        __syncthreads();

        // phase 2: [64,128] @ [128,64]
        float a2[4][4];
        #pragma unroll
        for (int i = 0; i < 4; i++)
            #pragma unroll
            for (int j = 0; j < 4; j++) a2[i][j] = 0.f;

        for (int k = 0; k < MH; k += 4) {
            const float4 bv0 = *(const float4*)&sW2[(k + 0) * HD + tx2 * 4];
            const float4 bv1 = *(const float4*)&sW2[(k + 1) * HD + tx2 * 4];
            const float4 bv2 = *(const float4*)&sW2[(k + 2) * HD + tx2 * 4];
            const float4 bv3 = *(const float4*)&sW2[(k + 3) * HD + tx2 * 4];
            #pragma unroll
            for (int i = 0; i < 4; i++) {
                const float4 av = *(const float4*)&sH[(ty2 * 4 + i) * 132 + k];
                a2[i][0] = fmaf(av.w, bv3.x, fmaf(av.z, bv2.x, fmaf(av.y, bv1.x, fmaf(av.x, bv0.x, a2[i][0]))));
                a2[i][1] = fmaf(av.w, bv3.y, fmaf(av.z, bv2.y, fmaf(av.y, bv1.y, fmaf(av.x, bv0.y, a2[i][1]))));
                a2[i][2] = fmaf(av.w, bv3.z, fmaf(av.z, bv2.z, fmaf(av.y, bv1.z, fmaf(av.x, bv0.z, a2[i][2]))));
                a2[i][3] = fmaf(av.w, bv3.w, fmaf(av.z, bv2.w, fmaf(av.y, bv1.w, fmaf(av.x, bv0.w, a2[i][3]))));
            }
        }

        // residual + bias -> sO
        #pragma unroll
        for (int i = 0; i < 4; i++) {
            const int r = ty2 * 4 + i;
            const int node = n0 + r;
            if (node < NN) {
                const float* hp = h + (size_t)node * HD + tx2 * 4;
                #pragma unroll
                for (int j = 0; j < 4; j++)
                    sO[r * 65 + tx2 * 4 + j] = a2[i][j] + b2r[j] + hp[j];
            }
        }
        __syncthreads();

        // per-row mean / rstd
        if (tid < TILE) {
            float s = 0.f, s2 = 0.f;
            #pragma unroll 8
            for (int c = 0; c < HD; c++) {
                float v = sO[tid * 65 + c];
                s += v;
                s2 = fmaf(v, v, s2);
            }
            float mu  = s * (1.f / HD);
            float var = fmaxf(s2 * (1.f / HD) - mu * mu, 0.f);
            sMu[tid] = mu;
            sRs[tid] = rsqrtf(var + 1e-5f);
        }
        __syncthreads();

        // normalized write
        for (int i = tid; i < TILE * HD; i += 256) {
            int r = i >> 6;
            int c = i & 63;
            int node = n0 + r;
            if (node < NN)
                out[(size_t)node * HD + c] =
                    (sO[r * 65 + c] - sMu[r]) * sRs[r] * sG[c] + sB[c];
        }
    }
}

// ---------------------------------------------------------------------------
extern "C" void kernel_launch(void* const* d_in, const int* in_sizes, int n_in,
                              void* d_out, int out_size)
{
    const float* h   = (const float*)d_in[0];
    const int*   ei  = (const int*)d_in[1];     // int32: JAX downcasts int64
    const float* ea  = (const float*)d_in[2];
    const float* eW1 = (const float*)d_in[3];
    const float* eb1 = (const float*)d_in[4];
    const float* eW2 = (const float*)d_in[5];
    const float* eb2 = (const float*)d_in[6];
    const float* nW1 = (const float*)d_in[7];
    const float* nb1 = (const float*)d_in[8];
    const float* nW2 = (const float*)d_in[9];
    const float* nb2 = (const float*)d_in[10];
    const float* lg  = (const float*)d_in[11];
    const float* lb  = (const float*)d_in[12];
    float*       out = (float*)d_out;

    const int smem_edge = (KIN * MH + MH * HD + TILE * KIN + TILE * 132) * 4
                          + 2 * TILE * 4;                         // 171,520 B
    const int smem_node = (MH * MH + MH * HD + TILE * MH + TILE * 132
                           + TILE * 65 + 4 * TILE) * 4;           // 182,528 B

    cudaFuncSetAttribute(edge_kernel, cudaFuncAttributeMaxDynamicSharedMemorySize, smem_edge);
    cudaFuncSetAttribute(node_kernel, cudaFuncAttributeMaxDynamicSharedMemorySize, smem_node);

    zero_agg_kernel<<<(NN * HD / 4 + 255) / 256, 256>>>();
    edge_kernel<<<296, 256, smem_edge>>>(h, ei, ea, eW1, eb1, eW2, eb2);
    node_kernel<<<296, 256, smem_node>>>(h, nW1, nb1, nW2, nb2, lg, lb, out);
}

// round 3
// speedup vs baseline: 1.6487x; 1.6487x over previous
#include <cuda_runtime.h>
#include <cstdint>

#define NN    50000
#define NE    800000
#define HD    64
#define KIN   136    // 2*HD + EDIM
#define KINP  140    // padded stride for sX (conflict-free A-frag loads)
#define MH    128
#define MHP   132    // padded stride for sH / sU
#define TILE  64

// scratch: aggregated messages per node
__device__ float g_agg[(size_t)NN * HD];

__device__ __forceinline__ float f2tf(float f) {
    uint32_t u;
    asm("cvt.rna.tf32.f32 %0, %1;" : "=r"(u) : "f"(f));
    return __uint_as_float(u);
}

__device__ __forceinline__ void mma_tf32(float c[4], const uint32_t a[4],
                                         uint32_t b0, uint32_t b1) {
    asm volatile(
        "mma.sync.aligned.m16n8k8.row.col.f32.tf32.tf32.f32 "
        "{%0,%1,%2,%3},{%4,%5,%6,%7},{%8,%9},{%0,%1,%2,%3};"
        : "+f"(c[0]), "+f"(c[1]), "+f"(c[2]), "+f"(c[3])
        : "r"(a[0]), "r"(a[1]), "r"(a[2]), "r"(a[3]), "r"(b0), "r"(b1));
}

// ---------------------------------------------------------------------------
__global__ void zero_agg_kernel() {
    int i = blockIdx.x * blockDim.x + threadIdx.x;
    const int n4 = NN * HD / 4;
    if (i < n4)
        reinterpret_cast<float4*>(g_agg)[i] = make_float4(0.f, 0.f, 0.f, 0.f);
}

// ---------------------------------------------------------------------------
// Edge kernel (tensor-core tf32)
//   X[64,136] = gather(h[src], h[dst], edge_attr)      (tf32 in SMEM)
//   Hd = relu(X @ eW1 + eb1)   [64,128]                (tf32 in SMEM)
//   M  = Hd @ eW2 + eb2        [64,64]
//   red.global.add.v2 M rows into g_agg[dst]
// ---------------------------------------------------------------------------
__global__ __launch_bounds__(256, 1)
void edge_kernel(const float* __restrict__ h,
                 const int* __restrict__ ei,
                 const float* __restrict__ ea,
                 const float* __restrict__ eW1, const float* __restrict__ eb1,
                 const float* __restrict__ eW2, const float* __restrict__ eb2)
{
    extern __shared__ float sm[];
    float* sW1 = sm;                       // 136*128, XOR-swizzled cols
    float* sW2 = sW1 + KIN * MH;           // 128*64,  XOR-swizzled cols
    float* sX  = sW2 + MH * HD;            // 64*140
    float* sH  = sX  + TILE * KINP;        // 64*132
    float* sB1 = sH  + TILE * MHP;         // 128
    float* sB2 = sB1 + MH;                 // 64
    int*   sSrc = (int*)(sB2 + HD);
    int*   sDst = sSrc + TILE;

    const int tid  = threadIdx.x;
    const int lane = tid & 31;
    const int w    = tid >> 5;
    const int lq   = lane >> 2;   // 0..7
    const int lr   = lane & 3;    // 0..3

    // weights: convert to tf32, XOR-swizzle columns for conflict-free B-frag loads
    for (int i = tid; i < KIN * MH; i += 256) {
        int r = i >> 7, n = i & 127;
        sW1[r * MH + (n ^ ((r & 3) << 3))] = f2tf(eW1[i]);
    }
    for (int i = tid; i < MH * HD; i += 256) {
        int r = i >> 6, n = i & 63;
        sW2[r * HD + (n ^ ((r & 3) << 3))] = f2tf(eW2[i]);
    }
    for (int i = tid; i < MH; i += 256) sB1[i] = eb1[i];
    if (tid < HD) sB2[tid] = eb2[tid];
    __syncthreads();

    // phase1 warp tile: (mh 0..1)->m32, (nq 0..3)->n32
    const int mh = w >> 2, nq = w & 3;
    // phase2 warp tile: (mq 0..3)->m16, (nh 0..1)->n32
    const int mq = w & 3, nh = w >> 2;

    // preload bias fragments
    float2 b1p[4], b2p[4];
    #pragma unroll
    for (int j = 0; j < 4; j++) {
        b1p[j] = *(const float2*)&sB1[nq * 32 + 8 * j + 2 * lr];
        b2p[j] = *(const float2*)&sB2[nh * 32 + 8 * j + 2 * lr];
    }

    const int numTiles = NE / TILE;
    for (int tile = blockIdx.x; tile < numTiles; tile += gridDim.x) {
        const int e0 = tile * TILE;
        __syncthreads();   // prior iteration done with sX/sH/sDst

        if (tid < TILE) {
            int s = ei[e0 + tid];
            int d = ei[NE + e0 + tid];
            sSrc[tid] = min(max(s, 0), NN - 1);
            sDst[tid] = min(max(d, 0), NN - 1);
        }
        __syncthreads();

        // gather X tile (tf32)
        for (int i = tid; i < TILE * KIN; i += 256) {
            int r = i / KIN;
            int k = i - r * KIN;
            float v;
            if (k < HD)          v = h[(size_t)sSrc[r] * HD + k];
            else if (k < 2 * HD) v = h[(size_t)sDst[r] * HD + (k - HD)];
            else                 v = ea[(size_t)(e0 + r) * 8 + (k - 2 * HD)];
            sX[r * KINP + k] = f2tf(v);
        }
        __syncthreads();

        // ---------------- phase 1: [64,136] @ [136,128] ----------------
        float c1[2][4][4];
        #pragma unroll
        for (int i = 0; i < 2; i++)
            #pragma unroll
            for (int j = 0; j < 4; j++)
                #pragma unroll
                for (int q = 0; q < 4; q++) c1[i][j][q] = 0.f;

        for (int k = 0; k < KIN; k += 8) {
            uint32_t a[2][4];
            #pragma unroll
            for (int i = 0; i < 2; i++) {
                int row = mh * 32 + 16 * i + lq;
                a[i][0] = __float_as_uint(sX[row * KINP + k + lr]);
                a[i][1] = __float_as_uint(sX[(row + 8) * KINP + k + lr]);
                a[i][2] = __float_as_uint(sX[row * KINP + k + 4 + lr]);
                a[i][3] = __float_as_uint(sX[(row + 8) * KINP + k + 4 + lr]);
            }
            #pragma unroll
            for (int j = 0; j < 4; j++) {
                int n0 = nq * 32 + 8 * j;
                int cs = (n0 + lq) ^ (lr << 3);
                uint32_t b0 = __float_as_uint(sW1[(k + lr) * MH + cs]);
                uint32_t b1 = __float_as_uint(sW1[(k + 4 + lr) * MH + cs]);
                mma_tf32(c1[0][j], a[0], b0, b1);
                mma_tf32(c1[1][j], a[1], b0, b1);
            }
        }

        // relu + bias -> sH (tf32)
        #pragma unroll
        for (int i = 0; i < 2; i++) {
            #pragma unroll
            for (int j = 0; j < 4; j++) {
                int row = mh * 32 + 16 * i + lq;
                int col = nq * 32 + 8 * j + 2 * lr;
                uint2 v0, v1;
                v0.x = __float_as_uint(f2tf(fmaxf(c1[i][j][0] + b1p[j].x, 0.f)));
                v0.y = __float_as_uint(f2tf(fmaxf(c1[i][j][1] + b1p[j].y, 0.f)));
                v1.x = __float_as_uint(f2tf(fmaxf(c1[i][j][2] + b1p[j].x, 0.f)));
                v1.y = __float_as_uint(f2tf(fmaxf(c1[i][j][3] + b1p[j].y, 0.f)));
                *(uint2*)&sH[row * MHP + col]       = v0;
                *(uint2*)&sH[(row + 8) * MHP + col] = v1;
            }
        }
        __syncthreads();

        // ---------------- phase 2: [64,128] @ [128,64] ----------------
        float c2[4][4];
        #pragma unroll
        for (int j = 0; j < 4; j++)
            #pragma unroll
            for (int q = 0; q < 4; q++) c2[j][q] = 0.f;

        const int m0 = mq * 16;
        for (int k = 0; k < MH; k += 8) {
            uint32_t a[4];
            int row = m0 + lq;
            a[0] = __float_as_uint(sH[row * MHP + k + lr]);
            a[1] = __float_as_uint(sH[(row + 8) * MHP + k + lr]);
            a[2] = __float_as_uint(sH[row * MHP + k + 4 + lr]);
            a[3] = __float_as_uint(sH[(row + 8) * MHP + k + 4 + lr]);
            #pragma unroll
            for (int j = 0; j < 4; j++) {
                int n0 = nh * 32 + 8 * j;
                int cs = (n0 + lq) ^ (lr << 3);
                uint32_t b0 = __float_as_uint(sW2[(k + lr) * HD + cs]);
                uint32_t b1 = __float_as_uint(sW2[(k + 4 + lr) * HD + cs]);
                mma_tf32(c2[j], a, b0, b1);
            }
        }

        // scatter-add C fragments directly (bias folded)
        {
            int r0 = m0 + lq;
            int r1 = r0 + 8;
            int d0 = sDst[r0], d1 = sDst[r1];
            #pragma unroll
            for (int j = 0; j < 4; j++) {
                int col = nh * 32 + 8 * j + 2 * lr;
                float u0 = c2[j][0] + b2p[j].x;
                float u1 = c2[j][1] + b2p[j].y;
                float u2 = c2[j][2] + b2p[j].x;
                float u3 = c2[j][3] + b2p[j].y;
                float* p0 = g_agg + (size_t)d0 * HD + col;
                float* p1 = g_agg + (size_t)d1 * HD + col;
                asm volatile("red.global.add.v2.f32 [%0], {%1, %2};"
                             :: "l"(p0), "f"(u0), "f"(u1) : "memory");
                asm volatile("red.global.add.v2.f32 [%0], {%1, %2};"
                             :: "l"(p1), "f"(u2), "f"(u3) : "memory");
            }
        }
    }
}

// ---------------------------------------------------------------------------
// Node kernel (tensor-core tf32)
//   U[64,128] = [h | agg]   -> Hd = relu(U@nW1+nb1) -> upd = Hd@nW2+nb2
//   out = LayerNorm(h + upd) * g + b
// ---------------------------------------------------------------------------
__global__ __launch_bounds__(256, 1)
void node_kernel(const float* __restrict__ h,
                 const float* __restrict__ nW1, const float* __restrict__ nb1,
                 const float* __restrict__ nW2, const float* __restrict__ nb2,
                 const float* __restrict__ lg,  const float* __restrict__ lb,
                 float* __restrict__ out)
{
    extern __shared__ float sm[];
    float* sW1 = sm;                       // 128*128 swizzled
    float* sW2 = sW1 + MH * MH;            // 128*64 swizzled
    float* sU  = sW2 + MH * HD;            // 64*132
    float* sH  = sU  + TILE * MHP;         // 64*132
    float* sO  = sH  + TILE * MHP;         // 64*65
    float* sB1 = sO  + TILE * 65;          // 128
    float* sB2 = sB1 + MH;                 // 64
    float* sG  = sB2 + HD;                 // 64
    float* sB  = sG  + HD;                 // 64
    float* sMu = sB  + HD;                 // 64
    float* sRs = sMu + TILE;               // 64

    const int tid  = threadIdx.x;
    const int lane = tid & 31;
    const int w    = tid >> 5;
    const int lq   = lane >> 2;
    const int lr   = lane & 3;

    for (int i = tid; i < MH * MH; i += 256) {
        int r = i >> 7, n = i & 127;
        sW1[r * MH + (n ^ ((r & 3) << 3))] = f2tf(nW1[i]);
    }
    for (int i = tid; i < MH * HD; i += 256) {
        int r = i >> 6, n = i & 63;
        sW2[r * HD + (n ^ ((r & 3) << 3))] = f2tf(nW2[i]);
    }
    for (int i = tid; i < MH; i += 256) sB1[i] = nb1[i];
    if (tid < HD) { sB2[tid] = nb2[tid]; sG[tid] = lg[tid]; sB[tid] = lb[tid]; }
    __syncthreads();

    const int mh = w >> 2, nq = w & 3;
    const int mq = w & 3,  nh = w >> 2;

    float2 b1p[4], b2p[4];
    #pragma unroll
    for (int j = 0; j < 4; j++) {
        b1p[j] = *(const float2*)&sB1[nq * 32 + 8 * j + 2 * lr];
        b2p[j] = *(const float2*)&sB2[nh * 32 + 8 * j + 2 * lr];
    }

    const int numTiles = (NN + TILE - 1) / TILE;
    for (int tile = blockIdx.x; tile < numTiles; tile += gridDim.x) {
        const int n0g = tile * TILE;
        __syncthreads();

        // gather U = [h | agg] (tf32)
        for (int i = tid; i < TILE * MH; i += 256) {
            int r = i >> 7;
            int k = i & 127;
            int node = min(n0g + r, NN - 1);
            float v = (k < HD) ? h[(size_t)node * HD + k]
                               : g_agg[(size_t)node * HD + (k - HD)];
            sU[r * MHP + k] = f2tf(v);
        }
        __syncthreads();

        // phase 1: [64,128] @ [128,128]
        float c1[2][4][4];
        #pragma unroll
        for (int i = 0; i < 2; i++)
            #pragma unroll
            for (int j = 0; j < 4; j++)
                #pragma unroll
                for (int q = 0; q < 4; q++) c1[i][j][q] = 0.f;

        for (int k = 0; k < MH; k += 8) {
            uint32_t a[2][4];
            #pragma unroll
            for (int i = 0; i < 2; i++) {
                int row = mh * 32 + 16 * i + lq;
                a[i][0] = __float_as_uint(sU[row * MHP + k + lr]);
                a[i][1] = __float_as_uint(sU[(row + 8) * MHP + k + lr]);
                a[i][2] = __float_as_uint(sU[row * MHP + k + 4 + lr]);
                a[i][3] = __float_as_uint(sU[(row + 8) * MHP + k + 4 + lr]);
            }
            #pragma unroll
            for (int j = 0; j < 4; j++) {
                int n0 = nq * 32 + 8 * j;
                int cs = (n0 + lq) ^ (lr << 3);
                uint32_t b0 = __float_as_uint(sW1[(k + lr) * MH + cs]);
                uint32_t b1 = __float_as_uint(sW1[(k + 4 + lr) * MH + cs]);
                mma_tf32(c1[0][j], a[0], b0, b1);
                mma_tf32(c1[1][j], a[1], b0, b1);
            }
        }

        #pragma unroll
        for (int i = 0; i < 2; i++) {
            #pragma unroll
            for (int j = 0; j < 4; j++) {
                int row = mh * 32 + 16 * i + lq;
                int col = nq * 32 + 8 * j + 2 * lr;
                uint2 v0, v1;
                v0.x = __float_as_uint(f2tf(fmaxf(c1[i][j][0] + b1p[j].x, 0.f)));
                v0.y = __float_as_uint(f2tf(fmaxf(c1[i][j][1] + b1p[j].y, 0.f)));
                v1.x = __float_as_uint(f2tf(fmaxf(c1[i][j][2] + b1p[j].x, 0.f)));
                v1.y = __float_as_uint(f2tf(fmaxf(c1[i][j][3] + b1p[j].y, 0.f)));
                *(uint2*)&sH[row * MHP + col]       = v0;
                *(uint2*)&sH[(row + 8) * MHP + col] = v1;
            }
        }
        __syncthreads();

        // phase 2: [64,128] @ [128,64]
        float c2[4][4];
        #pragma unroll
        for (int j = 0; j < 4; j++)
            #pragma unroll
            for (int q = 0; q < 4; q++) c2[j][q] = 0.f;

        const int m0 = mq * 16;
        for (int k = 0; k < MH; k += 8) {
            uint32_t a[4];
            int row = m0 + lq;
            a[0] = __float_as_uint(sH[row * MHP + k + lr]);
            a[1] = __float_as_uint(sH[(row + 8) * MHP + k + lr]);
            a[2] = __float_as_uint(sH[row * MHP + k + 4 + lr]);
            a[3] = __float_as_uint(sH[(row + 8) * MHP + k + 4 + lr]);
            #pragma unroll
            for (int j = 0; j < 4; j++) {
                int n0 = nh * 32 + 8 * j;
                int cs = (n0 + lq) ^ (lr << 3);
                uint32_t b0 = __float_as_uint(sW2[(k + lr) * HD + cs]);
                uint32_t b1 = __float_as_uint(sW2[(k + 4 + lr) * HD + cs]);
                mma_tf32(c2[j], a, b0, b1);
            }
        }

        // epilogue: residual + bias -> sO
        {
            int r0 = m0 + lq;
            int r1 = r0 + 8;
            int g0 = n0g + r0, g1 = n0g + r1;
            #pragma unroll
            for (int j = 0; j < 4; j++) {
                int col = nh * 32 + 8 * j + 2 * lr;
                if (g0 < NN) {
                    float2 hv = *(const float2*)&h[(size_t)g0 * HD + col];
                    sO[r0 * 65 + col]     = c2[j][0] + b2p[j].x + hv.x;
                    sO[r0 * 65 + col + 1] = c2[j][1] + b2p[j].y + hv.y;
                }
                if (g1 < NN) {
                    float2 hv = *(const float2*)&h[(size_t)g1 * HD + col];
                    sO[r1 * 65 + col]     = c2[j][2] + b2p[j].x + hv.x;
                    sO[r1 * 65 + col + 1] = c2[j][3] + b2p[j].y + hv.y;
                }
            }
        }
        __syncthreads();

        // per-row mean / rstd
        if (tid < TILE) {
            float s = 0.f, s2 = 0.f;
            #pragma unroll 8
            for (int c = 0; c < HD; c++) {
                float v = sO[tid * 65 + c];
                s += v;
                s2 = fmaf(v, v, s2);
            }
            float mu  = s * (1.f / HD);
            float var = fmaxf(s2 * (1.f / HD) - mu * mu, 0.f);
            sMu[tid] = mu;
            sRs[tid] = rsqrtf(var + 1e-5f);
        }
        __syncthreads();

        // normalized write
        for (int i = tid; i < TILE * HD; i += 256) {
            int r = i >> 6;
            int c = i & 63;
            int node = n0g + r;
            if (node < NN)
                out[(size_t)node * HD + c] =
                    (sO[r * 65 + c] - sMu[r]) * sRs[r] * sG[c] + sB[c];
        }
    }
}

// ---------------------------------------------------------------------------
extern "C" void kernel_launch(void* const* d_in, const int* in_sizes, int n_in,
                              void* d_out, int out_size)
{
    const float* h   = (const float*)d_in[0];
    const int*   ei  = (const int*)d_in[1];     // int32 (JAX default downcast)
    const float* ea  = (const float*)d_in[2];
    const float* eW1 = (const float*)d_in[3];
    const float* eb1 = (const float*)d_in[4];
    const float* eW2 = (const float*)d_in[5];
    const float* eb2 = (const float*)d_in[6];
    const float* nW1 = (const float*)d_in[7];
    const float* nb1 = (const float*)d_in[8];
    const float* nW2 = (const float*)d_in[9];
    const float* nb2 = (const float*)d_in[10];
    const float* lg  = (const float*)d_in[11];
    const float* lb  = (const float*)d_in[12];
    float*       out = (float*)d_out;

    const int smem_edge = (KIN * MH + MH * HD + TILE * KINP + TILE * MHP
                           + MH + HD) * 4 + 2 * TILE * 4;
    const int smem_node = (MH * MH + MH * HD + 2 * TILE * MHP + TILE * 65
                           + MH + 5 * HD + TILE) * 4;

    cudaFuncSetAttribute(edge_kernel, cudaFuncAttributeMaxDynamicSharedMemorySize, smem_edge);
    cudaFuncSetAttribute(node_kernel, cudaFuncAttributeMaxDynamicSharedMemorySize, smem_node);

    zero_agg_kernel<<<(NN * HD / 4 + 255) / 256, 256>>>();
    edge_kernel<<<148, 256, smem_edge>>>(h, ei, ea, eW1, eb1, eW2, eb2);
    node_kernel<<<148, 256, smem_node>>>(h, nW1, nb1, nW2, nb2, lg, lb, out);
}

// round 4
// speedup vs baseline: 4.0996x; 2.4866x over previous
#include <cuda_runtime.h>
#include <cstdint>

#define NN    50000
#define NE    800000
#define HD    64
#define MH    128
#define MHP   132    // padded stride (stride mod 32 == 4 -> conflict-free A-frags)

// scratch
__device__ float g_agg[(size_t)NN * HD];
__device__ float g_Pcat[(size_t)NN * 256];   // [ h@W_src | h@W_dst ]

__device__ __forceinline__ float f2tf(float f) {
    uint32_t u;
    asm("cvt.rna.tf32.f32 %0, %1;" : "=r"(u) : "f"(f));
    return __uint_as_float(u);
}

__device__ __forceinline__ void mma_tf32(float c[4], const uint32_t a[4],
                                         uint32_t b0, uint32_t b1) {
    asm volatile(
        "mma.sync.aligned.m16n8k8.row.col.f32.tf32.tf32.f32 "
        "{%0,%1,%2,%3},{%4,%5,%6,%7},{%8,%9},{%0,%1,%2,%3};"
        : "+f"(c[0]), "+f"(c[1]), "+f"(c[2]), "+f"(c[3])
        : "r"(a[0]), "r"(a[1]), "r"(a[2]), "r"(a[3]), "r"(b0), "r"(b1));
}

// ---------------------------------------------------------------------------
__global__ void zero_agg_kernel() {
    int i = blockIdx.x * blockDim.x + threadIdx.x;
    const int n4 = NN * HD / 4;
    if (i < n4)
        reinterpret_cast<float4*>(g_agg)[i] = make_float4(0.f, 0.f, 0.f, 0.f);
}

// ---------------------------------------------------------------------------
// prep: Pcat[n, 0:256] = h[n, 0:64] @ [W_src | W_dst]
//   W_src = eW1[0:64, :], W_dst = eW1[64:128, :]
// 128 nodes per block, 512 threads, warp grid 4(m32) x 4(n64)
// ---------------------------------------------------------------------------
__global__ __launch_bounds__(512, 1)
void prep_kernel(const float* __restrict__ h, const float* __restrict__ eW1)
{
    extern __shared__ float sm[];
    float* sW = sm;             // 64 x 256, col-swizzled
    float* sA = sW + 64 * 256;  // 128 x 68

    const int tid  = threadIdx.x;
    const int lane = tid & 31;
    const int w    = tid >> 5;
    const int lq   = lane >> 2;
    const int lr   = lane & 3;

    for (int i = tid; i < 64 * 256; i += 512) {
        int k = i >> 8, c = i & 255;
        float v = (c < MH) ? eW1[k * MH + c] : eW1[(64 + k) * MH + (c - MH)];
        sW[k * 256 + (c ^ ((k & 3) << 3))] = f2tf(v);
    }
    const int n0g = blockIdx.x * 128;
    for (int i = tid; i < 128 * 64; i += 512) {
        int r = i >> 6, c = i & 63;
        int node = min(n0g + r, NN - 1);
        sA[r * 68 + c] = f2tf(h[(size_t)node * HD + c]);
    }
    __syncthreads();

    const int mh = w >> 2, nc = w & 3;

    float acc[2][8][4];
    #pragma unroll
    for (int i = 0; i < 2; i++)
        #pragma unroll
        for (int j = 0; j < 8; j++)
            #pragma unroll
            for (int q = 0; q < 4; q++) acc[i][j][q] = 0.f;

    for (int k = 0; k < 64; k += 8) {
        uint32_t a[2][4];
        #pragma unroll
        for (int i = 0; i < 2; i++) {
            int row = mh * 32 + 16 * i + lq;
            a[i][0] = __float_as_uint(sA[row * 68 + k + lr]);
            a[i][1] = __float_as_uint(sA[(row + 8) * 68 + k + lr]);
            a[i][2] = __float_as_uint(sA[row * 68 + k + 4 + lr]);
            a[i][3] = __float_as_uint(sA[(row + 8) * 68 + k + 4 + lr]);
        }
        #pragma unroll
        for (int j = 0; j < 8; j++) {
            int n0 = nc * 64 + 8 * j;
            int cs = (n0 + lq) ^ (lr << 3);
            uint32_t b0 = __float_as_uint(sW[(k + lr) * 256 + cs]);
            uint32_t b1 = __float_as_uint(sW[(k + 4 + lr) * 256 + cs]);
            mma_tf32(acc[0][j], a[0], b0, b1);
            mma_tf32(acc[1][j], a[1], b0, b1);
        }
    }

    #pragma unroll
    for (int i = 0; i < 2; i++) {
        int r0 = mh * 32 + 16 * i + lq;
        int g0 = n0g + r0, g1 = g0 + 8;
        #pragma unroll
        for (int j = 0; j < 8; j++) {
            int col = nc * 64 + 8 * j + 2 * lr;
            if (g0 < NN) {
                float2 v = make_float2(acc[i][j][0], acc[i][j][1]);
                *(float2*)&g_Pcat[(size_t)g0 * 256 + col] = v;
            }
            if (g1 < NN) {
                float2 v = make_float2(acc[i][j][2], acc[i][j][3]);
                *(float2*)&g_Pcat[(size_t)g1 * 256 + col] = v;
            }
        }
    }
}

// ---------------------------------------------------------------------------
// Edge kernel, restructured:
//   Hd = relu( ea@W_ea  +  Pcat[src,0:128] + Pcat[dst,128:256] + b1 )
//   M  = Hd @ eW2 + eb2
//   red.global.add.v2 into g_agg[dst]
// TILE = 128 edges, 512 threads (16 warps), weights persistent in SMEM.
// ---------------------------------------------------------------------------
__global__ __launch_bounds__(512, 1)
void edge_kernel(const int* __restrict__ ei,
                 const float* __restrict__ ea,
                 const float* __restrict__ eW1, const float* __restrict__ eb1,
                 const float* __restrict__ eW2, const float* __restrict__ eb2)
{
    extern __shared__ float sm[];
    float* sWea = sm;                     // 8 x 128, col-swizzled (eW1 rows 128..135)
    float* sW2  = sWea + 8 * MH;          // 128 x 64, col-swizzled
    float* sEA  = sW2 + MH * HD;          // 128 x 12
    float* sH   = sEA + 128 * 12;         // 128 x 132
    float* sB1  = sH + 128 * MHP;         // 128
    float* sB2  = sB1 + MH;               // 64
    int*   sSrc = (int*)(sB2 + HD);       // 128
    int*   sDst = sSrc + 128;             // 128

    const int tid  = threadIdx.x;
    const int lane = tid & 31;
    const int w    = tid >> 5;
    const int lq   = lane >> 2;
    const int lr   = lane & 3;

    for (int i = tid; i < 8 * MH; i += 512) {
        int k = i >> 7, c = i & 127;
        sWea[k * MH + (c ^ ((k & 3) << 3))] = f2tf(eW1[(2 * HD + k) * MH + c]);
    }
    for (int i = tid; i < MH * HD; i += 512) {
        int r = i >> 6, n = i & 63;
        sW2[r * HD + (n ^ ((r & 3) << 3))] = f2tf(eW2[i]);
    }
    if (tid < MH) sB1[tid] = eb1[tid];
    if (tid < HD) sB2[tid] = eb2[tid];
    __syncthreads();

    // phase1 warp grid: 4 (m32) x 4 (n32); phase2: 4 (m32) x 4 (n16)
    const int mh = w >> 2, nq = w & 3;

    float2 b1p[4], b2p[2];
    #pragma unroll
    for (int j = 0; j < 4; j++)
        b1p[j] = *(const float2*)&sB1[nq * 32 + 8 * j + 2 * lr];
    #pragma unroll
    for (int j = 0; j < 2; j++)
        b2p[j] = *(const float2*)&sB2[nq * 16 + 8 * j + 2 * lr];

    const int numTiles = NE / 128;   // 6250 exact
    for (int tile = blockIdx.x; tile < numTiles; tile += gridDim.x) {
        const int e0 = tile * 128;
        __syncthreads();   // prior iteration done with sH / sEA / indices

        if (tid < 128) {
            int s = ei[e0 + tid];
            int d = ei[NE + e0 + tid];
            sSrc[tid] = min(max(s, 0), NN - 1);
            sDst[tid] = min(max(d, 0), NN - 1);
        }
        for (int i = tid; i < 128 * 8; i += 512) {
            int r = i >> 3, c = i & 7;
            sEA[r * 12 + c] = f2tf(ea[(size_t)e0 * 8 + i]);
        }
        __syncthreads();

        // ---- phase 1: [128,8] @ [8,128] + gathered Pcat + bias, relu ----
        float c1[2][4][4];
        #pragma unroll
        for (int i = 0; i < 2; i++)
            #pragma unroll
            for (int j = 0; j < 4; j++)
                #pragma unroll
                for (int q = 0; q < 4; q++) c1[i][j][q] = 0.f;

        {
            uint32_t a[2][4];
            #pragma unroll
            for (int i = 0; i < 2; i++) {
                int row = mh * 32 + 16 * i + lq;
                a[i][0] = __float_as_uint(sEA[row * 12 + lr]);
                a[i][1] = __float_as_uint(sEA[(row + 8) * 12 + lr]);
                a[i][2] = __float_as_uint(sEA[row * 12 + 4 + lr]);
                a[i][3] = __float_as_uint(sEA[(row + 8) * 12 + 4 + lr]);
            }
            #pragma unroll
            for (int j = 0; j < 4; j++) {
                int n0 = nq * 32 + 8 * j;
                int cs = (n0 + lq) ^ (lr << 3);
                uint32_t b0 = __float_as_uint(sWea[lr * MH + cs]);
                uint32_t b1 = __float_as_uint(sWea[(4 + lr) * MH + cs]);
                mma_tf32(c1[0][j], a[0], b0, b1);
                mma_tf32(c1[1][j], a[1], b0, b1);
            }
        }

        #pragma unroll
        for (int i = 0; i < 2; i++) {
            int r0 = mh * 32 + 16 * i + lq;
            int r1 = r0 + 8;
            const float* ps0 = g_Pcat + (size_t)sSrc[r0] * 256;
            const float* pd0 = g_Pcat + (size_t)sDst[r0] * 256 + MH;
            const float* ps1 = g_Pcat + (size_t)sSrc[r1] * 256;
            const float* pd1 = g_Pcat + (size_t)sDst[r1] * 256 + MH;
            #pragma unroll
            for (int j = 0; j < 4; j++) {
                int col = nq * 32 + 8 * j + 2 * lr;
                float2 s0 = *(const float2*)&ps0[col];
                float2 d0 = *(const float2*)&pd0[col];
                float2 s1 = *(const float2*)&ps1[col];
                float2 d1 = *(const float2*)&pd1[col];
                uint2 v0, v1;
                v0.x = __float_as_uint(f2tf(fmaxf(c1[i][j][0] + s0.x + d0.x + b1p[j].x, 0.f)));
                v0.y = __float_as_uint(f2tf(fmaxf(c1[i][j][1] + s0.y + d0.y + b1p[j].y, 0.f)));
                v1.x = __float_as_uint(f2tf(fmaxf(c1[i][j][2] + s1.x + d1.x + b1p[j].x, 0.f)));
                v1.y = __float_as_uint(f2tf(fmaxf(c1[i][j][3] + s1.y + d1.y + b1p[j].y, 0.f)));
                *(uint2*)&sH[r0 * MHP + col] = v0;
                *(uint2*)&sH[r1 * MHP + col] = v1;
            }
        }
        __syncthreads();

        // ---- phase 2: [128,128] @ [128,64] ----
        float c2[2][2][4];
        #pragma unroll
        for (int i = 0; i < 2; i++)
            #pragma unroll
            for (int j = 0; j < 2; j++)
                #pragma unroll
                for (int q = 0; q < 4; q++) c2[i][j][q] = 0.f;

        for (int k = 0; k < MH; k += 8) {
            uint32_t a[2][4];
            #pragma unroll
            for (int i = 0; i < 2; i++) {
                int row = mh * 32 + 16 * i + lq;
                a[i][0] = __float_as_uint(sH[row * MHP + k + lr]);
                a[i][1] = __float_as_uint(sH[(row + 8) * MHP + k + lr]);
                a[i][2] = __float_as_uint(sH[row * MHP + k + 4 + lr]);
                a[i][3] = __float_as_uint(sH[(row + 8) * MHP + k + 4 + lr]);
            }
            #pragma unroll
            for (int j = 0; j < 2; j++) {
                int n0 = nq * 16 + 8 * j;
                int cs = (n0 + lq) ^ (lr << 3);
                uint32_t b0 = __float_as_uint(sW2[(k + lr) * HD + cs]);
                uint32_t b1 = __float_as_uint(sW2[(k + 4 + lr) * HD + cs]);
                mma_tf32(c2[0][j], a[0], b0, b1);
                mma_tf32(c2[1][j], a[1], b0, b1);
            }
        }

        // scatter-add (bias folded)
        #pragma unroll
        for (int i = 0; i < 2; i++) {
            int r0 = mh * 32 + 16 * i + lq;
            int r1 = r0 + 8;
            int d0 = sDst[r0], d1 = sDst[r1];
            #pragma unroll
            for (int j = 0; j < 2; j++) {
                int col = nq * 16 + 8 * j + 2 * lr;
                float u0 = c2[i][j][0] + b2p[j].x;
                float u1 = c2[i][j][1] + b2p[j].y;
                float u2 = c2[i][j][2] + b2p[j].x;
                float u3 = c2[i][j][3] + b2p[j].y;
                float* p0 = g_agg + (size_t)d0 * HD + col;
                float* p1 = g_agg + (size_t)d1 * HD + col;
                asm volatile("red.global.add.v2.f32 [%0], {%1, %2};"
                             :: "l"(p0), "f"(u0), "f"(u1) : "memory");
                asm volatile("red.global.add.v2.f32 [%0], {%1, %2};"
                             :: "l"(p1), "f"(u2), "f"(u3) : "memory");
            }
        }
    }
}

// ---------------------------------------------------------------------------
// Node kernel (unchanged from R3): tf32 MMA, 64 nodes/tile, 256 threads
// ---------------------------------------------------------------------------
#define TILE 64
__global__ __launch_bounds__(256, 1)
void node_kernel(const float* __restrict__ h,
                 const float* __restrict__ nW1, const float* __restrict__ nb1,
                 const float* __restrict__ nW2, const float* __restrict__ nb2,
                 const float* __restrict__ lg,  const float* __restrict__ lb,
                 float* __restrict__ out)
{
    extern __shared__ float sm[];
    float* sW1 = sm;                       // 128*128 swizzled
    float* sW2 = sW1 + MH * MH;            // 128*64 swizzled
    float* sU  = sW2 + MH * HD;            // 64*132
    float* sH  = sU  + TILE * MHP;         // 64*132
    float* sO  = sH  + TILE * MHP;         // 64*65
    float* sB1 = sO  + TILE * 65;          // 128
    float* sB2 = sB1 + MH;                 // 64
    float* sG  = sB2 + HD;                 // 64
    float* sB  = sG  + HD;                 // 64
    float* sMu = sB  + HD;                 // 64
    float* sRs = sMu + TILE;               // 64

    const int tid  = threadIdx.x;
    const int lane = tid & 31;
    const int w    = tid >> 5;
    const int lq   = lane >> 2;
    const int lr   = lane & 3;

    for (int i = tid; i < MH * MH; i += 256) {
        int r = i >> 7, n = i & 127;
        sW1[r * MH + (n ^ ((r & 3) << 3))] = f2tf(nW1[i]);
    }
    for (int i = tid; i < MH * HD; i += 256) {
        int r = i >> 6, n = i & 63;
        sW2[r * HD + (n ^ ((r & 3) << 3))] = f2tf(nW2[i]);
    }
    for (int i = tid; i < MH; i += 256) sB1[i] = nb1[i];
    if (tid < HD) { sB2[tid] = nb2[tid]; sG[tid] = lg[tid]; sB[tid] = lb[tid]; }
    __syncthreads();

    const int mh = w >> 2, nq = w & 3;
    const int mq = w & 3,  nh = w >> 2;

    float2 b1p[4], b2p[4];
    #pragma unroll
    for (int j = 0; j < 4; j++) {
        b1p[j] = *(const float2*)&sB1[nq * 32 + 8 * j + 2 * lr];
        b2p[j] = *(const float2*)&sB2[nh * 32 + 8 * j + 2 * lr];
    }

    const int numTiles = (NN + TILE - 1) / TILE;
    for (int tile = blockIdx.x; tile < numTiles; tile += gridDim.x) {
        const int n0g = tile * TILE;
        __syncthreads();

        for (int i = tid; i < TILE * MH; i += 256) {
            int r = i >> 7;
            int k = i & 127;
            int node = min(n0g + r, NN - 1);
            float v = (k < HD) ? h[(size_t)node * HD + k]
                               : g_agg[(size_t)node * HD + (k - HD)];
            sU[r * MHP + k] = f2tf(v);
        }
        __syncthreads();

        float c1[2][4][4];
        #pragma unroll
        for (int i = 0; i < 2; i++)
            #pragma unroll
            for (int j = 0; j < 4; j++)
                #pragma unroll
                for (int q = 0; q < 4; q++) c1[i][j][q] = 0.f;

        for (int k = 0; k < MH; k += 8) {
            uint32_t a[2][4];
            #pragma unroll
            for (int i = 0; i < 2; i++) {
                int row = mh * 32 + 16 * i + lq;
                a[i][0] = __float_as_uint(sU[row * MHP + k + lr]);
                a[i][1] = __float_as_uint(sU[(row + 8) * MHP + k + lr]);
                a[i][2] = __float_as_uint(sU[row * MHP + k + 4 + lr]);
                a[i][3] = __float_as_uint(sU[(row + 8) * MHP + k + 4 + lr]);
            }
            #pragma unroll
            for (int j = 0; j < 4; j++) {
                int n0 = nq * 32 + 8 * j;
                int cs = (n0 + lq) ^ (lr << 3);
                uint32_t b0 = __float_as_uint(sW1[(k + lr) * MH + cs]);
                uint32_t b1 = __float_as_uint(sW1[(k + 4 + lr) * MH + cs]);
                mma_tf32(c1[0][j], a[0], b0, b1);
                mma_tf32(c1[1][j], a[1], b0, b1);
            }
        }

        #pragma unroll
        for (int i = 0; i < 2; i++) {
            #pragma unroll
            for (int j = 0; j < 4; j++) {
                int row = mh * 32 + 16 * i + lq;
                int col = nq * 32 + 8 * j + 2 * lr;
                uint2 v0, v1;
                v0.x = __float_as_uint(f2tf(fmaxf(c1[i][j][0] + b1p[j].x, 0.f)));
                v0.y = __float_as_uint(f2tf(fmaxf(c1[i][j][1] + b1p[j].y, 0.f)));
                v1.x = __float_as_uint(f2tf(fmaxf(c1[i][j][2] + b1p[j].x, 0.f)));
                v1.y = __float_as_uint(f2tf(fmaxf(c1[i][j][3] + b1p[j].y, 0.f)));
                *(uint2*)&sH[row * MHP + col]       = v0;
                *(uint2*)&sH[(row + 8) * MHP + col] = v1;
            }
        }
        __syncthreads();

        float c2[4][4];
        #pragma unroll
        for (int j = 0; j < 4; j++)
            #pragma unroll
            for (int q = 0; q < 4; q++) c2[j][q] = 0.f;

        const int m0 = mq * 16;
        for (int k = 0; k < MH; k += 8) {
            uint32_t a[4];
            int row = m0 + lq;
            a[0] = __float_as_uint(sH[row * MHP + k + lr]);
            a[1] = __float_as_uint(sH[(row + 8) * MHP + k + lr]);
            a[2] = __float_as_uint(sH[row * MHP + k + 4 + lr]);
            a[3] = __float_as_uint(sH[(row + 8) * MHP + k + 4 + lr]);
            #pragma unroll
            for (int j = 0; j < 4; j++) {
                int n0 = nh * 32 + 8 * j;
                int cs = (n0 + lq) ^ (lr << 3);
                uint32_t b0 = __float_as_uint(sW2[(k + lr) * HD + cs]);
                uint32_t b1 = __float_as_uint(sW2[(k + 4 + lr) * HD + cs]);
                mma_tf32(c2[j], a, b0, b1);
            }
        }

        {
            int r0 = m0 + lq;
            int r1 = r0 + 8;
            int g0 = n0g + r0, g1 = n0g + r1;
            #pragma unroll
            for (int j = 0; j < 4; j++) {
                int col = nh * 32 + 8 * j + 2 * lr;
                if (g0 < NN) {
                    float2 hv = *(const float2*)&h[(size_t)g0 * HD + col];
                    sO[r0 * 65 + col]     = c2[j][0] + b2p[j].x + hv.x;
                    sO[r0 * 65 + col + 1] = c2[j][1] + b2p[j].y + hv.y;
                }
                if (g1 < NN) {
                    float2 hv = *(const float2*)&h[(size_t)g1 * HD + col];
                    sO[r1 * 65 + col]     = c2[j][2] + b2p[j].x + hv.x;
                    sO[r1 * 65 + col + 1] = c2[j][3] + b2p[j].y + hv.y;
                }
            }
        }
        __syncthreads();

        if (tid < TILE) {
            float s = 0.f, s2 = 0.f;
            #pragma unroll 8
            for (int c = 0; c < HD; c++) {
                float v = sO[tid * 65 + c];
                s += v;
                s2 = fmaf(v, v, s2);
            }
            float mu  = s * (1.f / HD);
            float var = fmaxf(s2 * (1.f / HD) - mu * mu, 0.f);
            sMu[tid] = mu;
            sRs[tid] = rsqrtf(var + 1e-5f);
        }
        __syncthreads();

        for (int i = tid; i < TILE * HD; i += 256) {
            int r = i >> 6;
            int c = i & 63;
            int node = n0g + r;
            if (node < NN)
                out[(size_t)node * HD + c] =
                    (sO[r * 65 + c] - sMu[r]) * sRs[r] * sG[c] + sB[c];
        }
    }
}

// ---------------------------------------------------------------------------
extern "C" void kernel_launch(void* const* d_in, const int* in_sizes, int n_in,
                              void* d_out, int out_size)
{
    const float* h   = (const float*)d_in[0];
    const int*   ei  = (const int*)d_in[1];     // int32 (JAX default downcast)
    const float* ea  = (const float*)d_in[2];
    const float* eW1 = (const float*)d_in[3];
    const float* eb1 = (const float*)d_in[4];
    const float* eW2 = (const float*)d_in[5];
    const float* eb2 = (const float*)d_in[6];
    const float* nW1 = (const float*)d_in[7];
    const float* nb1 = (const float*)d_in[8];
    const float* nW2 = (const float*)d_in[9];
    const float* nb2 = (const float*)d_in[10];
    const float* lg  = (const float*)d_in[11];
    const float* lb  = (const float*)d_in[12];
    float*       out = (float*)d_out;

    const int smem_prep = (64 * 256 + 128 * 68) * 4;
    const int smem_edge = (8 * MH + MH * HD + 128 * 12 + 128 * MHP
                           + MH + HD) * 4 + 2 * 128 * 4;
    const int smem_node = (MH * MH + MH * HD + 2 * TILE * MHP + TILE * 65
                           + MH + 5 * HD + TILE) * 4;

    cudaFuncSetAttribute(prep_kernel, cudaFuncAttributeMaxDynamicSharedMemorySize, smem_prep);
    cudaFuncSetAttribute(edge_kernel, cudaFuncAttributeMaxDynamicSharedMemorySize, smem_edge);
    cudaFuncSetAttribute(node_kernel, cudaFuncAttributeMaxDynamicSharedMemorySize, smem_node);

    zero_agg_kernel<<<(NN * HD / 4 + 255) / 256, 256>>>();
    prep_kernel<<<(NN + 127) / 128, 512, smem_prep>>>(h, eW1);
    edge_kernel<<<148, 512, smem_edge>>>(ei, ea, eW1, eb1, eW2, eb2);
    node_kernel<<<148, 256, smem_node>>>(h, nW1, nb1, nW2, nb2, lg, lb, out);
}

// round 5
// speedup vs baseline: 4.6714x; 1.1395x over previous
#include <cuda_runtime.h>
#include <cstdint>

#define NN    50000
#define NE    800000
#define HD    64
#define MH    128
#define MHP   132    // padded stride (mod 32 == 4 -> conflict-free A-frags)
#define ET    64     // edge tile

// scratch
__device__ float g_agg[(size_t)NN * HD];
__device__ float g_Pcat[(size_t)NN * 256];   // [ h@W_src | h@W_dst ]

__device__ __forceinline__ float f2tf(float f) {
    uint32_t u;
    asm("cvt.rna.tf32.f32 %0, %1;" : "=r"(u) : "f"(f));
    return __uint_as_float(u);
}

__device__ __forceinline__ void mma_tf32(float c[4], const uint32_t a[4],
                                         uint32_t b0, uint32_t b1) {
    asm volatile(
        "mma.sync.aligned.m16n8k8.row.col.f32.tf32.tf32.f32 "
        "{%0,%1,%2,%3},{%4,%5,%6,%7},{%8,%9},{%0,%1,%2,%3};"
        : "+f"(c[0]), "+f"(c[1]), "+f"(c[2]), "+f"(c[3])
        : "r"(a[0]), "r"(a[1]), "r"(a[2]), "r"(a[3]), "r"(b0), "r"(b1));
}

// ---------------------------------------------------------------------------
// prep: Pcat[n, 0:256] = h[n] @ [W_src | W_dst]; also zeroes g_agg rows.
// 128 nodes/block, 512 threads, warp grid 4(m32) x 4(n64)
// ---------------------------------------------------------------------------
__global__ __launch_bounds__(512, 1)
void prep_kernel(const float* __restrict__ h, const float* __restrict__ eW1)
{
    extern __shared__ float sm[];
    float* sW = sm;             // 64 x 256, col-swizzled
    float* sA = sW + 64 * 256;  // 128 x 68

    const int tid  = threadIdx.x;
    const int lane = tid & 31;
    const int w    = tid >> 5;
    const int lq   = lane >> 2;
    const int lr   = lane & 3;
    const int n0g  = blockIdx.x * 128;

    // zero this block's g_agg rows
    for (int i = tid; i < 128 * 16; i += 512) {
        int r = i >> 4, c4 = i & 15;
        int node = n0g + r;
        if (node < NN)
            reinterpret_cast<float4*>(g_agg)[(size_t)node * 16 + c4] =
                make_float4(0.f, 0.f, 0.f, 0.f);
    }

    for (int i = tid; i < 64 * 256; i += 512) {
        int k = i >> 8, c = i & 255;
        float v = (c < MH) ? eW1[k * MH + c] : eW1[(64 + k) * MH + (c - MH)];
        sW[k * 256 + (c ^ ((k & 3) << 3))] = f2tf(v);
    }
    for (int i = tid; i < 128 * 64; i += 512) {
        int r = i >> 6, c = i & 63;
        int node = min(n0g + r, NN - 1);
        sA[r * 68 + c] = f2tf(h[(size_t)node * HD + c]);
    }
    __syncthreads();

    const int mh = w >> 2, nc = w & 3;

    float acc[2][8][4];
    #pragma unroll
    for (int i = 0; i < 2; i++)
        #pragma unroll
        for (int j = 0; j < 8; j++)
            #pragma unroll
            for (int q = 0; q < 4; q++) acc[i][j][q] = 0.f;

    for (int k = 0; k < 64; k += 8) {
        uint32_t a[2][4];
        #pragma unroll
        for (int i = 0; i < 2; i++) {
            int row = mh * 32 + 16 * i + lq;
            a[i][0] = __float_as_uint(sA[row * 68 + k + lr]);
            a[i][1] = __float_as_uint(sA[(row + 8) * 68 + k + lr]);
            a[i][2] = __float_as_uint(sA[row * 68 + k + 4 + lr]);
            a[i][3] = __float_as_uint(sA[(row + 8) * 68 + k + 4 + lr]);
        }
        #pragma unroll
        for (int j = 0; j < 8; j++) {
            int n0 = nc * 64 + 8 * j;
            int cs = (n0 + lq) ^ (lr << 3);
            uint32_t b0 = __float_as_uint(sW[(k + lr) * 256 + cs]);
            uint32_t b1 = __float_as_uint(sW[(k + 4 + lr) * 256 + cs]);
            mma_tf32(acc[0][j], a[0], b0, b1);
            mma_tf32(acc[1][j], a[1], b0, b1);
        }
    }

    #pragma unroll
    for (int i = 0; i < 2; i++) {
        int r0 = mh * 32 + 16 * i + lq;
        int g0 = n0g + r0, g1 = g0 + 8;
        #pragma unroll
        for (int j = 0; j < 8; j++) {
            int col = nc * 64 + 8 * j + 2 * lr;
            if (g0 < NN)
                *(float2*)&g_Pcat[(size_t)g0 * 256 + col] =
                    make_float2(acc[i][j][0], acc[i][j][1]);
            if (g1 < NN)
                *(float2*)&g_Pcat[(size_t)g1 * 256 + col] =
                    make_float2(acc[i][j][2], acc[i][j][3]);
        }
    }
}

// ---------------------------------------------------------------------------
// Edge kernel: 64-edge tiles, 256 threads, 2 CTAs/SM, next-tile reg prefetch.
//   Hd = relu( ea@W_ea + Pcat[src,0:128] + Pcat[dst,128:256] + b1 )
//   M  = Hd @ eW2 + eb2  ->  red.global.add.v2 into g_agg[dst]
// ---------------------------------------------------------------------------
__global__ __launch_bounds__(256, 2)
void edge_kernel(const int* __restrict__ ei,
                 const float* __restrict__ ea,
                 const float* __restrict__ eW1, const float* __restrict__ eb1,
                 const float* __restrict__ eW2, const float* __restrict__ eb2)
{
    extern __shared__ float sm[];
    float* sWea = sm;                     // 8 x 128, col-swizzled
    float* sW2  = sWea + 8 * MH;          // 128 x 64, col-swizzled
    float* sEA  = sW2 + MH * HD;          // 64 x 12
    float* sH   = sEA + ET * 12;          // 64 x 132
    float* sB1  = sH + ET * MHP;          // 128
    float* sB2  = sB1 + MH;               // 64
    int*   sSrc = (int*)(sB2 + HD);       // 64
    int*   sDst = sSrc + ET;              // 64

    const int tid  = threadIdx.x;
    const int lane = tid & 31;
    const int w    = tid >> 5;
    const int lq   = lane >> 2;
    const int lr   = lane & 3;

    for (int i = tid; i < 8 * MH; i += 256) {
        int k = i >> 7, c = i & 127;
        sWea[k * MH + (c ^ ((k & 3) << 3))] = f2tf(eW1[(2 * HD + k) * MH + c]);
    }
    for (int i = tid; i < MH * HD; i += 256) {
        int r = i >> 6, n = i & 63;
        sW2[r * HD + (n ^ ((r & 3) << 3))] = f2tf(eW2[i]);
    }
    if (tid < MH) sB1[tid] = eb1[tid];
    if (tid < HD) sB2[tid] = eb2[tid];

    const int mh = w >> 2;   // 0..1 -> m32
    const int nq = w & 3;    // 0..3 -> n32 (phase1) / n16 (phase2)

    float2 b1p[4], b2p[2];
    #pragma unroll
    for (int j = 0; j < 4; j++) b1p[j] = *(const float2*)&eb1[nq * 32 + 8 * j + 2 * lr];
    #pragma unroll
    for (int j = 0; j < 2; j++) b2p[j] = *(const float2*)&eb2[nq * 16 + 8 * j + 2 * lr];

    const int numTiles = NE / ET;   // 12500 exact

    // prefetch first tile into registers
    int pS = 0, pD = 0;
    float2 pEA = make_float2(0.f, 0.f);
    int t = blockIdx.x;
    if (t < numTiles) {
        const int e0 = t * ET;
        if (tid < ET) {
            pS = ei[e0 + tid];
            pD = ei[NE + e0 + tid];
        }
        pEA = *(const float2*)&ea[(size_t)e0 * 8 + 2 * tid];
    }

    for (; t < numTiles; t += gridDim.x) {
        const int e0 = t * ET;
        __syncthreads();   // smem free (weights done / prev tile done)

        // commit prefetched tile to smem
        if (tid < ET) {
            sSrc[tid] = min(max(pS, 0), NN - 1);
            sDst[tid] = min(max(pD, 0), NN - 1);
        }
        {
            int idx = 2 * tid;
            int r = idx >> 3, c = idx & 7;
            sEA[r * 12 + c]     = f2tf(pEA.x);
            sEA[r * 12 + c + 1] = f2tf(pEA.y);
        }
        __syncthreads();

        // issue next tile's loads (hidden under this tile's compute)
        int tn = t + gridDim.x;
        if (tn < numTiles) {
            const int en = tn * ET;
            if (tid < ET) {
                pS = ei[en + tid];
                pD = ei[NE + en + tid];
            }
            pEA = *(const float2*)&ea[(size_t)en * 8 + 2 * tid];
        }

        // ---- phase 1: [64,8] @ [8,128] ----
        float c1[2][4][4];
        #pragma unroll
        for (int i = 0; i < 2; i++)
            #pragma unroll
            for (int j = 0; j < 4; j++)
                #pragma unroll
                for (int q = 0; q < 4; q++) c1[i][j][q] = 0.f;

        {
            uint32_t a[2][4];
            #pragma unroll
            for (int i = 0; i < 2; i++) {
                int row = mh * 32 + 16 * i + lq;
                a[i][0] = __float_as_uint(sEA[row * 12 + lr]);
                a[i][1] = __float_as_uint(sEA[(row + 8) * 12 + lr]);
                a[i][2] = __float_as_uint(sEA[row * 12 + 4 + lr]);
                a[i][3] = __float_as_uint(sEA[(row + 8) * 12 + 4 + lr]);
            }
            #pragma unroll
            for (int j = 0; j < 4; j++) {
                int n0 = nq * 32 + 8 * j;
                int cs = (n0 + lq) ^ (lr << 3);
                uint32_t b0 = __float_as_uint(sWea[lr * MH + cs]);
                uint32_t b1 = __float_as_uint(sWea[(4 + lr) * MH + cs]);
                mma_tf32(c1[0][j], a[0], b0, b1);
                mma_tf32(c1[1][j], a[1], b0, b1);
            }
        }

        // gathered Pcat + bias, relu -> sH
        #pragma unroll
        for (int i = 0; i < 2; i++) {
            int r0 = mh * 32 + 16 * i + lq;
            int r1 = r0 + 8;
            const float* ps0 = g_Pcat + (size_t)sSrc[r0] * 256;
            const float* pd0 = g_Pcat + (size_t)sDst[r0] * 256 + MH;
            const float* ps1 = g_Pcat + (size_t)sSrc[r1] * 256;
            const float* pd1 = g_Pcat + (size_t)sDst[r1] * 256 + MH;
            #pragma unroll
            for (int j = 0; j < 4; j++) {
                int col = nq * 32 + 8 * j + 2 * lr;
                float2 s0 = *(const float2*)&ps0[col];
                float2 d0 = *(const float2*)&pd0[col];
                float2 s1 = *(const float2*)&ps1[col];
                float2 d1 = *(const float2*)&pd1[col];
                uint2 v0, v1;
                v0.x = __float_as_uint(f2tf(fmaxf(c1[i][j][0] + s0.x + d0.x + b1p[j].x, 0.f)));
                v0.y = __float_as_uint(f2tf(fmaxf(c1[i][j][1] + s0.y + d0.y + b1p[j].y, 0.f)));
                v1.x = __float_as_uint(f2tf(fmaxf(c1[i][j][2] + s1.x + d1.x + b1p[j].x, 0.f)));
                v1.y = __float_as_uint(f2tf(fmaxf(c1[i][j][3] + s1.y + d1.y + b1p[j].y, 0.f)));
                *(uint2*)&sH[r0 * MHP + col] = v0;
                *(uint2*)&sH[r1 * MHP + col] = v1;
            }
        }
        __syncthreads();

        // ---- phase 2: [64,128] @ [128,64] ----
        float c2[2][2][4];
        #pragma unroll
        for (int i = 0; i < 2; i++)
            #pragma unroll
            for (int j = 0; j < 2; j++)
                #pragma unroll
                for (int q = 0; q < 4; q++) c2[i][j][q] = 0.f;

        for (int k = 0; k < MH; k += 8) {
            uint32_t a[2][4];
            #pragma unroll
            for (int i = 0; i < 2; i++) {
                int row = mh * 32 + 16 * i + lq;
                a[i][0] = __float_as_uint(sH[row * MHP + k + lr]);
                a[i][1] = __float_as_uint(sH[(row + 8) * MHP + k + lr]);
                a[i][2] = __float_as_uint(sH[row * MHP + k + 4 + lr]);
                a[i][3] = __float_as_uint(sH[(row + 8) * MHP + k + 4 + lr]);
            }
            #pragma unroll
            for (int j = 0; j < 2; j++) {
                int n0 = nq * 16 + 8 * j;
                int cs = (n0 + lq) ^ (lr << 3);
                uint32_t b0 = __float_as_uint(sW2[(k + lr) * HD + cs]);
                uint32_t b1 = __float_as_uint(sW2[(k + 4 + lr) * HD + cs]);
                mma_tf32(c2[0][j], a[0], b0, b1);
                mma_tf32(c2[1][j], a[1], b0, b1);
            }
        }

        // scatter-add (bias folded)
        #pragma unroll
        for (int i = 0; i < 2; i++) {
            int r0 = mh * 32 + 16 * i + lq;
            int r1 = r0 + 8;
            int d0 = sDst[r0], d1 = sDst[r1];
            #pragma unroll
            for (int j = 0; j < 2; j++) {
                int col = nq * 16 + 8 * j + 2 * lr;
                float u0 = c2[i][j][0] + b2p[j].x;
                float u1 = c2[i][j][1] + b2p[j].y;
                float u2 = c2[i][j][2] + b2p[j].x;
                float u3 = c2[i][j][3] + b2p[j].y;
                float* p0 = g_agg + (size_t)d0 * HD + col;
                float* p1 = g_agg + (size_t)d1 * HD + col;
                asm volatile("red.global.add.v2.f32 [%0], {%1, %2};"
                             :: "l"(p0), "f"(u0), "f"(u1) : "memory");
                asm volatile("red.global.add.v2.f32 [%0], {%1, %2};"
                             :: "l"(p1), "f"(u2), "f"(u3) : "memory");
            }
        }
    }
}

// ---------------------------------------------------------------------------
// Node kernel (unchanged): tf32 MMA, 64 nodes/tile, 256 threads
// ---------------------------------------------------------------------------
#define TILE 64
__global__ __launch_bounds__(256, 1)
void node_kernel(const float* __restrict__ h,
                 const float* __restrict__ nW1, const float* __restrict__ nb1,
                 const float* __restrict__ nW2, const float* __restrict__ nb2,
                 const float* __restrict__ lg,  const float* __restrict__ lb,
                 float* __restrict__ out)
{
    extern __shared__ float sm[];
    float* sW1 = sm;                       // 128*128 swizzled
    float* sW2 = sW1 + MH * MH;            // 128*64 swizzled
    float* sU  = sW2 + MH * HD;            // 64*132
    float* sH  = sU  + TILE * MHP;         // 64*132
    float* sO  = sH  + TILE * MHP;         // 64*65
    float* sB1 = sO  + TILE * 65;          // 128
    float* sB2 = sB1 + MH;                 // 64
    float* sG  = sB2 + HD;                 // 64
    float* sB  = sG  + HD;                 // 64
    float* sMu = sB  + HD;                 // 64
    float* sRs = sMu + TILE;               // 64

    const int tid  = threadIdx.x;
    const int lane = tid & 31;
    const int w    = tid >> 5;
    const int lq   = lane >> 2;
    const int lr   = lane & 3;

    for (int i = tid; i < MH * MH; i += 256) {
        int r = i >> 7, n = i & 127;
        sW1[r * MH + (n ^ ((r & 3) << 3))] = f2tf(nW1[i]);
    }
    for (int i = tid; i < MH * HD; i += 256) {
        int r = i >> 6, n = i & 63;
        sW2[r * HD + (n ^ ((r & 3) << 3))] = f2tf(nW2[i]);
    }
    for (int i = tid; i < MH; i += 256) sB1[i] = nb1[i];
    if (tid < HD) { sB2[tid] = nb2[tid]; sG[tid] = lg[tid]; sB[tid] = lb[tid]; }
    __syncthreads();

    const int mh = w >> 2, nq = w & 3;
    const int mq = w & 3,  nh = w >> 2;

    float2 b1p[4], b2p[4];
    #pragma unroll
    for (int j = 0; j < 4; j++) {
        b1p[j] = *(const float2*)&sB1[nq * 32 + 8 * j + 2 * lr];
        b2p[j] = *(const float2*)&sB2[nh * 32 + 8 * j + 2 * lr];
    }

    const int numTiles = (NN + TILE - 1) / TILE;
    for (int tile = blockIdx.x; tile < numTiles; tile += gridDim.x) {
        const int n0g = tile * TILE;
        __syncthreads();

        for (int i = tid; i < TILE * MH; i += 256) {
            int r = i >> 7;
            int k = i & 127;
            int node = min(n0g + r, NN - 1);
            float v = (k < HD) ? h[(size_t)node * HD + k]
                               : g_agg[(size_t)node * HD + (k - HD)];
            sU[r * MHP + k] = f2tf(v);
        }
        __syncthreads();

        float c1[2][4][4];
        #pragma unroll
        for (int i = 0; i < 2; i++)
            #pragma unroll
            for (int j = 0; j < 4; j++)
                #pragma unroll
                for (int q = 0; q < 4; q++) c1[i][j][q] = 0.f;

        for (int k = 0; k < MH; k += 8) {
            uint32_t a[2][4];
            #pragma unroll
            for (int i = 0; i < 2; i++) {
                int row = mh * 32 + 16 * i + lq;
                a[i][0] = __float_as_uint(sU[row * MHP + k + lr]);
                a[i][1] = __float_as_uint(sU[(row + 8) * MHP + k + lr]);
                a[i][2] = __float_as_uint(sU[row * MHP + k + 4 + lr]);
                a[i][3] = __float_as_uint(sU[(row + 8) * MHP + k + 4 + lr]);
            }
            #pragma unroll
            for (int j = 0; j < 4; j++) {
                int n0 = nq * 32 + 8 * j;
                int cs = (n0 + lq) ^ (lr << 3);
                uint32_t b0 = __float_as_uint(sW1[(k + lr) * MH + cs]);
                uint32_t b1 = __float_as_uint(sW1[(k + 4 + lr) * MH + cs]);
                mma_tf32(c1[0][j], a[0], b0, b1);
                mma_tf32(c1[1][j], a[1], b0, b1);
            }
        }

        #pragma unroll
        for (int i = 0; i < 2; i++) {
            #pragma unroll
            for (int j = 0; j < 4; j++) {
                int row = mh * 32 + 16 * i + lq;
                int col = nq * 32 + 8 * j + 2 * lr;
                uint2 v0, v1;
                v0.x = __float_as_uint(f2tf(fmaxf(c1[i][j][0] + b1p[j].x, 0.f)));
                v0.y = __float_as_uint(f2tf(fmaxf(c1[i][j][1] + b1p[j].y, 0.f)));
                v1.x = __float_as_uint(f2tf(fmaxf(c1[i][j][2] + b1p[j].x, 0.f)));
                v1.y = __float_as_uint(f2tf(fmaxf(c1[i][j][3] + b1p[j].y, 0.f)));
                *(uint2*)&sH[row * MHP + col]       = v0;
                *(uint2*)&sH[(row + 8) * MHP + col] = v1;
            }
        }
        __syncthreads();

        float c2[4][4];
        #pragma unroll
        for (int j = 0; j < 4; j++)
            #pragma unroll
            for (int q = 0; q < 4; q++) c2[j][q] = 0.f;

        const int m0 = mq * 16;
        for (int k = 0; k < MH; k += 8) {
            uint32_t a[4];
            int row = m0 + lq;
            a[0] = __float_as_uint(sH[row * MHP + k + lr]);
            a[1] = __float_as_uint(sH[(row + 8) * MHP + k + lr]);
            a[2] = __float_as_uint(sH[row * MHP + k + 4 + lr]);
            a[3] = __float_as_uint(sH[(row + 8) * MHP + k + 4 + lr]);
            #pragma unroll
            for (int j = 0; j < 4; j++) {
                int n0 = nh * 32 + 8 * j;
                int cs = (n0 + lq) ^ (lr << 3);
                uint32_t b0 = __float_as_uint(sW2[(k + lr) * HD + cs]);
                uint32_t b1 = __float_as_uint(sW2[(k + 4 + lr) * HD + cs]);
                mma_tf32(c2[j], a, b0, b1);
            }
        }

        {
            int r0 = m0 + lq;
            int r1 = r0 + 8;
            int g0 = n0g + r0, g1 = n0g + r1;
            #pragma unroll
            for (int j = 0; j < 4; j++) {
                int col = nh * 32 + 8 * j + 2 * lr;
                if (g0 < NN) {
                    float2 hv = *(const float2*)&h[(size_t)g0 * HD + col];
                    sO[r0 * 65 + col]     = c2[j][0] + b2p[j].x + hv.x;
                    sO[r0 * 65 + col + 1] = c2[j][1] + b2p[j].y + hv.y;
                }
                if (g1 < NN) {
                    float2 hv = *(const float2*)&h[(size_t)g1 * HD + col];
                    sO[r1 * 65 + col]     = c2[j][2] + b2p[j].x + hv.x;
                    sO[r1 * 65 + col + 1] = c2[j][3] + b2p[j].y + hv.y;
                }
            }
        }
        __syncthreads();

        if (tid < TILE) {
            float s = 0.f, s2 = 0.f;
            #pragma unroll 8
            for (int c = 0; c < HD; c++) {
                float v = sO[tid * 65 + c];
                s += v;
                s2 = fmaf(v, v, s2);
            }
            float mu  = s * (1.f / HD);
            float var = fmaxf(s2 * (1.f / HD) - mu * mu, 0.f);
            sMu[tid] = mu;
            sRs[tid] = rsqrtf(var + 1e-5f);
        }
        __syncthreads();

        for (int i = tid; i < TILE * HD; i += 256) {
            int r = i >> 6;
            int c = i & 63;
            int node = n0g + r;
            if (node < NN)
                out[(size_t)node * HD + c] =
                    (sO[r * 65 + c] - sMu[r]) * sRs[r] * sG[c] + sB[c];
        }
    }
}

// ---------------------------------------------------------------------------
extern "C" void kernel_launch(void* const* d_in, const int* in_sizes, int n_in,
                              void* d_out, int out_size)
{
    const float* h   = (const float*)d_in[0];
    const int*   ei  = (const int*)d_in[1];     // int32 (JAX default downcast)
    const float* ea  = (const float*)d_in[2];
    const float* eW1 = (const float*)d_in[3];
    const float* eb1 = (const float*)d_in[4];
    const float* eW2 = (const float*)d_in[5];
    const float* eb2 = (const float*)d_in[6];
    const float* nW1 = (const float*)d_in[7];
    const float* nb1 = (const float*)d_in[8];
    const float* nW2 = (const float*)d_in[9];
    const float* nb2 = (const float*)d_in[10];
    const float* lg  = (const float*)d_in[11];
    const float* lb  = (const float*)d_in[12];
    float*       out = (float*)d_out;

    const int smem_prep = (64 * 256 + 128 * 68) * 4;
    const int smem_edge = (8 * MH + MH * HD + ET * 12 + ET * MHP
                           + MH + HD) * 4 + 2 * ET * 4;
    const int smem_node = (MH * MH + MH * HD + 2 * TILE * MHP + TILE * 65
                           + MH + 5 * HD + TILE) * 4;

    cudaFuncSetAttribute(prep_kernel, cudaFuncAttributeMaxDynamicSharedMemorySize, smem_prep);
    cudaFuncSetAttribute(edge_kernel, cudaFuncAttributeMaxDynamicSharedMemorySize, smem_edge);
    cudaFuncSetAttribute(node_kernel, cudaFuncAttributeMaxDynamicSharedMemorySize, smem_node);

    prep_kernel<<<(NN + 127) / 128, 512, smem_prep>>>(h, eW1);
    edge_kernel<<<296, 256, smem_edge>>>(ei, ea, eW1, eb1, eW2, eb2);
    node_kernel<<<148, 256, smem_node>>>(h, nW1, nb1, nW2, nb2, lg, lb, out);
}